// round 1
// baseline (speedup 1.0000x reference)
#include <cuda_runtime.h>
#include <cuda_bf16.h>
#include <math.h>

#define NN 100000
#define EE 1600000
#define DH 64   // hidden dim (D1 = D2 = 64)

// ---------------- scratch (no allocations allowed) ----------------
__device__ int   g_rowptr[NN + 1];
__device__ int   g_wp[NN];        // counts, then write pointers
__device__ int   g_dst[EE];       // dst sorted by src (CSR adjacency)
__device__ float g_p[NN];         // per-node attention scalar
__device__ float g_v[(size_t)NN * DH]; // per-node value rows
__device__ float g_h1[(size_t)NN * DH];// layer-1 output

// ---------------- CSR build ----------------
__global__ void k_zero_counts() {
    int i = blockIdx.x * blockDim.x + threadIdx.x;
    if (i < NN) g_wp[i] = 0;
}

__global__ void k_count(const int* __restrict__ src) {
    int j = blockIdx.x * blockDim.x + threadIdx.x;
    if (j < EE) atomicAdd(&g_wp[src[j]], 1);
}

// single-block chunked exclusive scan of g_wp -> g_rowptr (and reset g_wp to row starts)
__global__ void k_scan() {
    __shared__ int tsum[1024];
    const int tid = threadIdx.x;
    const int CH = (NN + 1023) / 1024;  // 98
    const int base = tid * CH;
    int s = 0;
    for (int i = 0; i < CH; i++) {
        int idx = base + i;
        if (idx < NN) s += g_wp[idx];
    }
    tsum[tid] = s;
    __syncthreads();
    // Hillis-Steele inclusive scan over 1024 partials
    for (int off = 1; off < 1024; off <<= 1) {
        int v = 0;
        if (tid >= off) v = tsum[tid - off];
        __syncthreads();
        tsum[tid] += v;
        __syncthreads();
    }
    int run = (tid == 0) ? 0 : tsum[tid - 1];
    for (int i = 0; i < CH; i++) {
        int idx = base + i;
        if (idx < NN) {
            int c = g_wp[idx];
            g_rowptr[idx] = run;
            g_wp[idx] = run;   // write pointer for scatter
            run += c;
        }
    }
    if (tid == 0) g_rowptr[NN] = EE;
}

__global__ void k_scatter(const int* __restrict__ src, const int* __restrict__ dst) {
    int j = blockIdx.x * blockDim.x + threadIdx.x;
    if (j < EE) {
        int pos = atomicAdd(&g_wp[src[j]], 1);
        g_dst[pos] = dst[j];
    }
}

// ---------------- fused node transform ----------------
// Computes, for every node i:
//   v[i,:]  = tanh(x[i] @ Wv^T + bv)          (stored to g_v)
//   p[i]    = sum_t tanh(x[i]@Wa[t]+ba[t]) * we[t]   (stored to g_p)
// Block = 128 threads; thread t<64 owns "a" output t (feeds p), t>=64 owns v output t-64.
// W resident in smem for the whole (persistent) block; 16-node x tiles.
template <int DIN>
__global__ void node_transform(const float* __restrict__ x,
                               const float* __restrict__ Wa, const float* __restrict__ ba,
                               const float* __restrict__ we,
                               const float* __restrict__ Wv, const float* __restrict__ bv)
{
    constexpr int TN = 16;
    constexpr int WSTRIDE = DIN + 4;  // pad: conflict-free float4 rows
    extern __shared__ float sm[];
    float* Ws   = sm;                       // 128 * WSTRIDE
    float* Xs   = Ws + 128 * WSTRIDE;       // TN * DIN
    float* wes  = Xs + TN * DIN;            // 64
    float* pred = wes + 64;                 // 2 * TN (per-warp partial p)

    const int tid = threadIdx.x;

    // load both weight matrices into smem (rows 0..63 = Wa, 64..127 = Wv)
    for (int i = tid; i < 64 * DIN; i += 128) {
        int r = i / DIN, c = i % DIN;
        Ws[r * WSTRIDE + c]        = Wa[i];
        Ws[(r + 64) * WSTRIDE + c] = Wv[i];
    }
    if (tid < 64) wes[tid] = we[tid];
    const float bias = (tid < 64) ? ba[tid] : bv[tid - 64];

    const int numTiles = (NN + TN - 1) / TN;
    const float4* wr = reinterpret_cast<const float4*>(Ws + tid * WSTRIDE);

    for (int tile = blockIdx.x; tile < numTiles; tile += gridDim.x) {
        const int n0 = tile * TN;
        __syncthreads();  // protect Xs/pred from previous tile's readers
        for (int i = tid; i < TN * DIN; i += 128) {
            int n = i / DIN, c = i - n * DIN;
            int node = n0 + n;
            Xs[i] = (node < NN) ? x[(size_t)node * DIN + c] : 0.f;
        }
        __syncthreads();

        float acc[TN];
        #pragma unroll
        for (int n = 0; n < TN; n++) acc[n] = bias;

        #pragma unroll 2
        for (int k4 = 0; k4 < DIN / 4; k4++) {
            float4 w = wr[k4];
            #pragma unroll
            for (int n = 0; n < TN; n++) {
                float4 xv = reinterpret_cast<const float4*>(Xs + n * DIN)[k4];
                acc[n] += w.x * xv.x + w.y * xv.y + w.z * xv.z + w.w * xv.w;
            }
        }

        #pragma unroll
        for (int n = 0; n < TN; n++) acc[n] = tanhf(acc[n]);

        if (tid >= 64) {
            const int c = tid - 64;
            #pragma unroll
            for (int n = 0; n < TN; n++) {
                int node = n0 + n;
                if (node < NN) g_v[(size_t)node * DH + c] = acc[n];
            }
        } else {
            const float wv = wes[tid];
            #pragma unroll
            for (int n = 0; n < TN; n++) acc[n] *= wv;
            #pragma unroll
            for (int o = 16; o; o >>= 1) {
                #pragma unroll
                for (int n = 0; n < TN; n++)
                    acc[n] += __shfl_xor_sync(0xffffffffu, acc[n], o);
            }
            if ((tid & 31) == 0) {
                int w_ = tid >> 5;  // 0 or 1
                #pragma unroll
                for (int n = 0; n < TN; n++) pred[w_ * TN + n] = acc[n];
            }
        }
        __syncthreads();
        if (tid < TN) {
            int node = n0 + tid;
            if (node < NN) g_p[node] = pred[tid] + pred[TN + tid];
        }
    }
}

// ---------------- per-row softmax + aggregation + std-normalize ----------------
// One warp per row. Pass 1: edge-parallel max of e = tanh(p_s + p_d + be).
// Pass 2: edge-sequential (warp-wide) exp/sum + weighted gather of v[dst].
__global__ void gat_rows(const float* __restrict__ beptr, float* __restrict__ out)
{
    const int warp = (blockIdx.x * blockDim.x + threadIdx.x) >> 5;
    const int lane = threadIdx.x & 31;
    if (warp >= NN) return;

    const float be = __ldg(beptr);
    const int s = g_rowptr[warp];
    const int e = g_rowptr[warp + 1];
    const float pi = __ldg(&g_p[warp]);

    float m = -1e30f;
    for (int j = s + lane; j < e; j += 32)
        m = fmaxf(m, tanhf(pi + __ldg(&g_p[g_dst[j]]) + be));
    #pragma unroll
    for (int o = 16; o; o >>= 1) m = fmaxf(m, __shfl_xor_sync(0xffffffffu, m, o));

    float acc0 = 0.f, acc1 = 0.f, den = 0.f;
    for (int j = s; j < e; j++) {
        const int dd = g_dst[j];                         // broadcast load
        const float w = __expf(tanhf(pi + g_p[dd] + be) - m);
        den += w;
        const float* vr = g_v + (size_t)dd * DH;
        acc0 += w * vr[lane];                            // coalesced 128B
        acc1 += w * vr[lane + 32];                       // coalesced 128B
    }
    const float inv = 1.f / den;
    acc0 *= inv; acc1 *= inv;

    // std over the 64 values (ddof = 1), then divide
    float sum = acc0 + acc1;
    #pragma unroll
    for (int o = 16; o; o >>= 1) sum += __shfl_xor_sync(0xffffffffu, sum, o);
    const float mean = sum * (1.f / 64.f);
    float d0 = acc0 - mean, d1 = acc1 - mean;
    float ss = d0 * d0 + d1 * d1;
    #pragma unroll
    for (int o = 16; o; o >>= 1) ss += __shfl_xor_sync(0xffffffffu, ss, o);
    const float istd = rsqrtf(ss * (1.f / 63.f));

    out[(size_t)warp * DH + lane]      = acc0 * istd;
    out[(size_t)warp * DH + 32 + lane] = acc1 * istd;
}

// ---------------- launch ----------------
extern "C" void kernel_launch(void* const* d_in, const int* in_sizes, int n_in,
                              void* d_out, int out_size)
{
    const float* h   = (const float*)d_in[0];
    const int*   ei  = (const int*)d_in[1];
    const int*   src = ei;
    const int*   dst = ei + EE;
    const float* W11 = (const float*)d_in[2];
    const float* b11 = (const float*)d_in[3];
    const float* W12 = (const float*)d_in[4];
    const float* b12 = (const float*)d_in[5];
    const float* W13 = (const float*)d_in[6];
    const float* b13 = (const float*)d_in[7];
    const float* W21 = (const float*)d_in[8];
    const float* b21 = (const float*)d_in[9];
    const float* W22 = (const float*)d_in[10];
    const float* b22 = (const float*)d_in[11];
    const float* W23 = (const float*)d_in[12];
    const float* b23 = (const float*)d_in[13];
    float* out = (float*)d_out;

    // ---- CSR build (reused by both layers) ----
    k_zero_counts<<<(NN + 255) / 256, 256>>>();
    k_count<<<(EE + 255) / 256, 256>>>(src);
    k_scan<<<1, 1024>>>();
    k_scatter<<<(EE + 255) / 256, 256>>>(src, dst);

    // ---- layer 1 ----
    {
        constexpr int DIN = 128;
        size_t smem = (size_t)(128 * (DIN + 4) + 16 * DIN + 64 + 32) * sizeof(float);
        cudaFuncSetAttribute(node_transform<DIN>,
                             cudaFuncAttributeMaxDynamicSharedMemorySize, (int)smem);
        node_transform<DIN><<<444, 128, smem>>>(h, W11, b11, W12, W13, b13);
        gat_rows<<<(NN * 32 + 255) / 256, 256>>>(b12, g_h1);
    }

    // ---- layer 2 ----
    {
        constexpr int DIN = 64;
        size_t smem = (size_t)(128 * (DIN + 4) + 16 * DIN + 64 + 32) * sizeof(float);
        cudaFuncSetAttribute(node_transform<DIN>,
                             cudaFuncAttributeMaxDynamicSharedMemorySize, (int)smem);
        node_transform<DIN><<<592, 128, smem>>>(g_h1, W21, b21, W22, W23, b23);
        gat_rows<<<(NN * 32 + 255) / 256, 256>>>(b22, out);
    }
}

// round 2
// speedup vs baseline: 1.0543x; 1.0543x over previous
#include <cuda_runtime.h>
#include <cuda_bf16.h>
#include <math.h>

#define NN 100000
#define EE 1600000
#define DH 64   // hidden dim (D1 = D2 = 64)

// ---------------- scratch (no allocations allowed) ----------------
__device__ int   g_rowptr[NN + 1];
__device__ int   g_wp[NN];        // counts, then write pointers
__device__ int   g_dst[EE];       // dst sorted by src (CSR adjacency)
__device__ float g_p[NN];         // per-node attention scalar
__device__ float g_v[(size_t)NN * DH]; // per-node value rows
__device__ float g_h1[(size_t)NN * DH];// layer-1 output

// ---------------- helpers ----------------
__device__ __forceinline__ float tanha(float x) {
    float y;
    asm("tanh.approx.f32 %0, %1;" : "=f"(y) : "f"(x));
    return y;
}

#define FMA2(d, a, b) \
    asm("fma.rn.f32x2 %0, %1, %2, %0;" : "+l"(d) : "l"(a), "l"(b))

__device__ __forceinline__ unsigned long long pack_dup(float f) {
    unsigned long long r;
    unsigned u = __float_as_uint(f);
    asm("mov.b64 %0, {%1, %2};" : "=l"(r) : "r"(u), "r"(u));
    return r;
}
__device__ __forceinline__ void unpack2(unsigned long long v, float& lo, float& hi) {
    unsigned a, b;
    asm("mov.b64 {%0, %1}, %2;" : "=r"(a), "=r"(b) : "l"(v));
    lo = __uint_as_float(a);
    hi = __uint_as_float(b);
}

// ---------------- CSR build ----------------
__global__ void k_zero_counts() {
    int i = blockIdx.x * blockDim.x + threadIdx.x;
    if (i < NN) g_wp[i] = 0;
}

__global__ void k_count(const int* __restrict__ src) {
    int j = blockIdx.x * blockDim.x + threadIdx.x;
    if (j < EE) atomicAdd(&g_wp[src[j]], 1);
}

__global__ void k_scan() {
    __shared__ int tsum[1024];
    const int tid = threadIdx.x;
    const int CH = (NN + 1023) / 1024;
    const int base = tid * CH;
    int s = 0;
    for (int i = 0; i < CH; i++) {
        int idx = base + i;
        if (idx < NN) s += g_wp[idx];
    }
    tsum[tid] = s;
    __syncthreads();
    for (int off = 1; off < 1024; off <<= 1) {
        int v = 0;
        if (tid >= off) v = tsum[tid - off];
        __syncthreads();
        tsum[tid] += v;
        __syncthreads();
    }
    int run = (tid == 0) ? 0 : tsum[tid - 1];
    for (int i = 0; i < CH; i++) {
        int idx = base + i;
        if (idx < NN) {
            int c = g_wp[idx];
            g_rowptr[idx] = run;
            g_wp[idx] = run;
            run += c;
        }
    }
    if (tid == 0) g_rowptr[NN] = EE;
}

__global__ void k_scatter(const int* __restrict__ src, const int* __restrict__ dst) {
    int j = blockIdx.x * blockDim.x + threadIdx.x;
    if (j < EE) {
        int pos = atomicAdd(&g_wp[src[j]], 1);
        g_dst[pos] = dst[j];
    }
}

// ---------------- fused node transform, register-tiled ----------------
// C[128 outs][node] where outs 0..63 = "a" rows (feed p), 64..127 = v rows.
// CTA = 256 threads: go = tid&15 (16 groups x TM=8 outs), gn = tid>>4 (16 groups x TN=8 nodes).
// Smem: Wt[k][out] (transposed, resident) + Xt[k][node] (transposed, per tile), stride WS=132.
// Inner loop: 4x LDS.128 + 32x fma.rn.f32x2 per k  ->  1.0 B per FMA-lane.
template <int DIN>
__global__ __launch_bounds__(256, 1)
void node_transform2(const float* __restrict__ x,
                     const float* __restrict__ Wa, const float* __restrict__ ba,
                     const float* __restrict__ we,
                     const float* __restrict__ Wv, const float* __restrict__ bv)
{
    constexpr int WS = 132;
    extern __shared__ float sm[];
    float* Wt = sm;                 // DIN * WS
    float* Xt = sm + DIN * WS;      // DIN * WS

    const int tid  = threadIdx.x;
    const int go   = tid & 15;
    const int gn   = tid >> 4;
    const int out0 = go * 8;
    const int nb0  = gn * 8;

    // Load both weight matrices transposed into smem (cols 0..63 = Wa rows, 64..127 = Wv rows)
    for (int i = tid; i < 64 * DIN; i += 256) {
        int r = i / DIN, k = i - r * DIN;
        Wt[k * WS + r]      = Wa[i];
        Wt[k * WS + 64 + r] = Wv[i];
    }
    // Per-thread bias / we for owned output rows
    float bias[8], wev[8];
    #pragma unroll
    for (int m = 0; m < 8; m++) {
        int r = out0 + m;
        bias[m] = (r < 64) ? ba[r] : bv[r - 64];
        wev[m]  = (r < 64) ? we[r] : 0.f;
    }

    const int numTiles = (NN + 127) / 128;
    for (int tile = blockIdx.x; tile < numTiles; tile += gridDim.x) {
        const int n0 = tile * 128;
        __syncthreads();  // protect Xt from previous tile's readers
        for (int i = tid; i < 128 * DIN; i += 256) {
            int n = i / DIN, k = i - n * DIN;
            int node = n0 + n;
            Xt[k * WS + n] = (node < NN) ? x[(size_t)node * DIN + k] : 0.f;
        }
        __syncthreads();

        // acc[m][j] = packed (C[out0+m][nb0+2j], C[out0+m][nb0+2j+1])
        unsigned long long acc[8][4];
        #pragma unroll
        for (int m = 0; m < 8; m++) {
            unsigned long long bb = pack_dup(bias[m]);
            acc[m][0] = bb; acc[m][1] = bb; acc[m][2] = bb; acc[m][3] = bb;
        }

        #pragma unroll 4
        for (int k = 0; k < DIN; k++) {
            const float4* wp = reinterpret_cast<const float4*>(Wt + k * WS + out0);
            float4 w0 = wp[0], w1 = wp[1];
            const ulonglong2* xp = reinterpret_cast<const ulonglong2*>(Xt + k * WS + nb0);
            ulonglong2 xa = xp[0], xb = xp[1];

            unsigned long long wq[8];
            wq[0] = pack_dup(w0.x); wq[1] = pack_dup(w0.y);
            wq[2] = pack_dup(w0.z); wq[3] = pack_dup(w0.w);
            wq[4] = pack_dup(w1.x); wq[5] = pack_dup(w1.y);
            wq[6] = pack_dup(w1.z); wq[7] = pack_dup(w1.w);

            #pragma unroll
            for (int m = 0; m < 8; m++) {
                FMA2(acc[m][0], wq[m], xa.x);
                FMA2(acc[m][1], wq[m], xa.y);
                FMA2(acc[m][2], wq[m], xb.x);
                FMA2(acc[m][3], wq[m], xb.y);
            }
        }

        // epilogue: tanh, write v rows, reduce p
        float pacc[8];
        #pragma unroll
        for (int n = 0; n < 8; n++) pacc[n] = 0.f;

        #pragma unroll
        for (int j = 0; j < 4; j++) {
            float c0[8], c1[8];
            #pragma unroll
            for (int m = 0; m < 8; m++) {
                float f0, f1;
                unpack2(acc[m][j], f0, f1);
                f0 = tanha(f0); f1 = tanha(f1);
                c0[m] = f0; c1[m] = f1;
                pacc[2 * j]     += f0 * wev[m];
                pacc[2 * j + 1] += f1 * wev[m];
            }
            if (go >= 8) {  // v rows: cols out0-64 .. +8 for nodes n0+nb0+2j, +2j+1
                int node0 = n0 + nb0 + 2 * j;
                int c = out0 - 64;
                if (node0 < NN) {
                    float4* d = reinterpret_cast<float4*>(g_v + (size_t)node0 * DH + c);
                    d[0] = make_float4(c0[0], c0[1], c0[2], c0[3]);
                    d[1] = make_float4(c0[4], c0[5], c0[6], c0[7]);
                }
                if (node0 + 1 < NN) {
                    float4* d = reinterpret_cast<float4*>(g_v + (size_t)(node0 + 1) * DH + c);
                    d[0] = make_float4(c1[0], c1[1], c1[2], c1[3]);
                    d[1] = make_float4(c1[4], c1[5], c1[6], c1[7]);
                }
            }
        }

        // reduce pacc across go = 0..7 (lane bits 0..2), all lanes participate
        #pragma unroll
        for (int o = 1; o < 8; o <<= 1) {
            #pragma unroll
            for (int n = 0; n < 8; n++)
                pacc[n] += __shfl_xor_sync(0xffffffffu, pacc[n], o);
        }
        if (go == 0) {
            int node0 = n0 + nb0;
            #pragma unroll
            for (int n = 0; n < 8; n++)
                if (node0 + n < NN) g_p[node0 + n] = pacc[n];
        }
    }
}

// ---------------- per-row softmax + aggregation + std-normalize ----------------
__global__ void gat_rows(const float* __restrict__ beptr, float* __restrict__ out)
{
    const int warp = (blockIdx.x * blockDim.x + threadIdx.x) >> 5;
    const int lane = threadIdx.x & 31;
    if (warp >= NN) return;

    const float be = __ldg(beptr);
    const int s = g_rowptr[warp];
    const int e = g_rowptr[warp + 1];
    const float pi = __ldg(&g_p[warp]);

    float m = -1e30f;
    for (int j = s + lane; j < e; j += 32)
        m = fmaxf(m, tanha(pi + __ldg(&g_p[g_dst[j]]) + be));
    #pragma unroll
    for (int o = 16; o; o >>= 1) m = fmaxf(m, __shfl_xor_sync(0xffffffffu, m, o));

    float acc0 = 0.f, acc1 = 0.f, den = 0.f;
    for (int j = s; j < e; j++) {
        const int dd = g_dst[j];
        const float w = __expf(tanha(pi + g_p[dd] + be) - m);
        den += w;
        const float* vr = g_v + (size_t)dd * DH;
        acc0 += w * vr[lane];
        acc1 += w * vr[lane + 32];
    }
    const float inv = 1.f / den;
    acc0 *= inv; acc1 *= inv;

    float sum = acc0 + acc1;
    #pragma unroll
    for (int o = 16; o; o >>= 1) sum += __shfl_xor_sync(0xffffffffu, sum, o);
    const float mean = sum * (1.f / 64.f);
    float d0 = acc0 - mean, d1 = acc1 - mean;
    float ss = d0 * d0 + d1 * d1;
    #pragma unroll
    for (int o = 16; o; o >>= 1) ss += __shfl_xor_sync(0xffffffffu, ss, o);
    const float istd = rsqrtf(ss * (1.f / 63.f));

    out[(size_t)warp * DH + lane]      = acc0 * istd;
    out[(size_t)warp * DH + 32 + lane] = acc1 * istd;
}

// ---------------- launch ----------------
extern "C" void kernel_launch(void* const* d_in, const int* in_sizes, int n_in,
                              void* d_out, int out_size)
{
    const float* h   = (const float*)d_in[0];
    const int*   ei  = (const int*)d_in[1];
    const int*   src = ei;
    const int*   dst = ei + EE;
    const float* W11 = (const float*)d_in[2];
    const float* b11 = (const float*)d_in[3];
    const float* W12 = (const float*)d_in[4];
    const float* b12 = (const float*)d_in[5];
    const float* W13 = (const float*)d_in[6];
    const float* b13 = (const float*)d_in[7];
    const float* W21 = (const float*)d_in[8];
    const float* b21 = (const float*)d_in[9];
    const float* W22 = (const float*)d_in[10];
    const float* b22 = (const float*)d_in[11];
    const float* W23 = (const float*)d_in[12];
    const float* b23 = (const float*)d_in[13];
    float* out = (float*)d_out;

    // ---- CSR build (reused by both layers) ----
    k_zero_counts<<<(NN + 255) / 256, 256>>>();
    k_count<<<(EE + 255) / 256, 256>>>(src);
    k_scan<<<1, 1024>>>();
    k_scatter<<<(EE + 255) / 256, 256>>>(src, dst);

    // ---- layer 1 ----
    {
        constexpr int DIN = 128;
        size_t smem = (size_t)(2 * DIN * 132) * sizeof(float);
        cudaFuncSetAttribute(node_transform2<DIN>,
                             cudaFuncAttributeMaxDynamicSharedMemorySize, (int)smem);
        node_transform2<DIN><<<148, 256, smem>>>(h, W11, b11, W12, W13, b13);
        gat_rows<<<(NN * 32 + 255) / 256, 256>>>(b12, g_h1);
    }

    // ---- layer 2 ----
    {
        constexpr int DIN = 64;
        size_t smem = (size_t)(2 * DIN * 132) * sizeof(float);
        cudaFuncSetAttribute(node_transform2<DIN>,
                             cudaFuncAttributeMaxDynamicSharedMemorySize, (int)smem);
        node_transform2<DIN><<<296, 256, smem>>>(g_h1, W21, b21, W22, W23, b23);
        gat_rows<<<(NN * 32 + 255) / 256, 256>>>(b22, out);
    }
}

// round 16
// speedup vs baseline: 1.3419x; 1.2728x over previous
#include <cuda_runtime.h>
#include <cuda_bf16.h>
#include <math.h>

#define NN 100000
#define EE 1600000
#define DH 64

#define SCAN_B 1024
#define SCAN_G ((NN + SCAN_B - 1) / SCAN_B)   // 98

// ---------------- scratch ----------------
__device__ int   g_rowptr[NN + 1];
__device__ int   g_wp[NN];
__device__ int   g_dst[EE];
__device__ int   g_bsum[SCAN_G];
__device__ int   g_boff[SCAN_G];
__device__ float g_p[NN];
__device__ float g_v[(size_t)NN * DH];
__device__ float g_h1[(size_t)NN * DH];

// ---------------- helpers ----------------
__device__ __forceinline__ float tanha(float x) {
    float y;
    asm("tanh.approx.f32 %0, %1;" : "=f"(y) : "f"(x));
    return y;
}

#define FMA2(d, a, b) \
    asm("fma.rn.f32x2 %0, %1, %2, %0;" : "+l"(d) : "l"(a), "l"(b))

__device__ __forceinline__ unsigned long long pack_dup(float f) {
    unsigned long long r;
    unsigned u = __float_as_uint(f);
    asm("mov.b64 %0, {%1, %2};" : "=l"(r) : "r"(u), "r"(u));
    return r;
}
__device__ __forceinline__ void unpack2(unsigned long long v, float& lo, float& hi) {
    unsigned a, b;
    asm("mov.b64 {%0, %1}, %2;" : "=r"(a), "=r"(b) : "l"(v));
    lo = __uint_as_float(a);
    hi = __uint_as_float(b);
}

// ---------------- CSR build ----------------
__global__ void k_zero_counts() {
    int i = blockIdx.x * blockDim.x + threadIdx.x;
    if (i < NN) g_wp[i] = 0;
}

__global__ void k_count(const int* __restrict__ src) {
    int j = blockIdx.x * blockDim.x + threadIdx.x;
    if (j < EE) atomicAdd(&g_wp[src[j]], 1);
}

// block-level exclusive scan of g_wp; per-block exclusive prefixes -> g_rowptr,
// block totals -> g_bsum
__global__ void k_blockscan() {
    __shared__ int wsum[32];
    const int tid = threadIdx.x;
    const int i = blockIdx.x * SCAN_B + tid;
    const int lane = tid & 31, warp = tid >> 5;

    int v = (i < NN) ? g_wp[i] : 0;
    int s = v;
    #pragma unroll
    for (int o = 1; o < 32; o <<= 1) {
        int t = __shfl_up_sync(0xffffffffu, s, o);
        if (lane >= o) s += t;
    }
    if (lane == 31) wsum[warp] = s;
    __syncthreads();
    if (warp == 0) {
        int ws = wsum[lane];
        #pragma unroll
        for (int o = 1; o < 32; o <<= 1) {
            int t = __shfl_up_sync(0xffffffffu, ws, o);
            if (lane >= o) ws += t;
        }
        wsum[lane] = ws;
    }
    __syncthreads();
    int base = (warp == 0) ? 0 : wsum[warp - 1];
    int excl = base + s - v;
    if (i < NN) g_rowptr[i] = excl;
    if (tid == SCAN_B - 1) g_bsum[blockIdx.x] = excl + v;
}

// single block: exclusive scan of g_bsum (98 values) -> g_boff
__global__ void k_bsum_scan() {
    __shared__ int wsum[4];
    const int tid = threadIdx.x;       // 128 threads
    const int lane = tid & 31, warp = tid >> 5;
    int v = (tid < SCAN_G) ? g_bsum[tid] : 0;
    int s = v;
    #pragma unroll
    for (int o = 1; o < 32; o <<= 1) {
        int t = __shfl_up_sync(0xffffffffu, s, o);
        if (lane >= o) s += t;
    }
    if (lane == 31) wsum[warp] = s;
    __syncthreads();
    int base = 0;
    for (int w = 0; w < warp; w++) base += wsum[w];
    if (tid < SCAN_G) g_boff[tid] = base + s - v;
}

__global__ void k_addoff() {
    const int i = blockIdx.x * SCAN_B + threadIdx.x;
    if (i < NN) {
        int r = g_rowptr[i] + g_boff[blockIdx.x];
        g_rowptr[i] = r;
        g_wp[i] = r;
    }
    if (i == 0) g_rowptr[NN] = EE;
}

__global__ void k_scatter(const int* __restrict__ src, const int* __restrict__ dst) {
    int j = blockIdx.x * blockDim.x + threadIdx.x;
    if (j < EE) {
        int pos = atomicAdd(&g_wp[src[j]], 1);
        g_dst[pos] = dst[j];
    }
}

// ---------------- fused node transform (register-tiled, FFMA2) ----------------
template <int DIN>
__global__ __launch_bounds__(256, 1)
void node_transform2(const float* __restrict__ x,
                     const float* __restrict__ Wa, const float* __restrict__ ba,
                     const float* __restrict__ we,
                     const float* __restrict__ Wv, const float* __restrict__ bv)
{
    constexpr int WS = 132;
    extern __shared__ float sm[];
    float* Wt = sm;
    float* Xt = sm + DIN * WS;

    const int tid  = threadIdx.x;
    const int go   = tid & 15;
    const int gn   = tid >> 4;
    const int out0 = go * 8;
    const int nb0  = gn * 8;

    for (int i = tid; i < 64 * DIN; i += 256) {
        int r = i / DIN, k = i - r * DIN;
        Wt[k * WS + r]      = Wa[i];
        Wt[k * WS + 64 + r] = Wv[i];
    }
    float bias[8], wev[8];
    #pragma unroll
    for (int m = 0; m < 8; m++) {
        int r = out0 + m;
        bias[m] = (r < 64) ? ba[r] : bv[r - 64];
        wev[m]  = (r < 64) ? we[r] : 0.f;
    }

    const int numTiles = (NN + 127) / 128;
    for (int tile = blockIdx.x; tile < numTiles; tile += gridDim.x) {
        const int n0 = tile * 128;
        __syncthreads();
        for (int i = tid; i < 128 * DIN; i += 256) {
            int n = i / DIN, k = i - n * DIN;
            int node = n0 + n;
            Xt[k * WS + n] = (node < NN) ? x[(size_t)node * DIN + k] : 0.f;
        }
        __syncthreads();

        unsigned long long acc[8][4];
        #pragma unroll
        for (int m = 0; m < 8; m++) {
            unsigned long long bb = pack_dup(bias[m]);
            acc[m][0] = bb; acc[m][1] = bb; acc[m][2] = bb; acc[m][3] = bb;
        }

        #pragma unroll 4
        for (int k = 0; k < DIN; k++) {
            const float4* wp = reinterpret_cast<const float4*>(Wt + k * WS + out0);
            float4 w0 = wp[0], w1 = wp[1];
            const ulonglong2* xp = reinterpret_cast<const ulonglong2*>(Xt + k * WS + nb0);
            ulonglong2 xa = xp[0], xb = xp[1];

            unsigned long long wq[8];
            wq[0] = pack_dup(w0.x); wq[1] = pack_dup(w0.y);
            wq[2] = pack_dup(w0.z); wq[3] = pack_dup(w0.w);
            wq[4] = pack_dup(w1.x); wq[5] = pack_dup(w1.y);
            wq[6] = pack_dup(w1.z); wq[7] = pack_dup(w1.w);

            #pragma unroll
            for (int m = 0; m < 8; m++) {
                FMA2(acc[m][0], wq[m], xa.x);
                FMA2(acc[m][1], wq[m], xa.y);
                FMA2(acc[m][2], wq[m], xb.x);
                FMA2(acc[m][3], wq[m], xb.y);
            }
        }

        float pacc[8];
        #pragma unroll
        for (int n = 0; n < 8; n++) pacc[n] = 0.f;

        #pragma unroll
        for (int j = 0; j < 4; j++) {
            float c0[8], c1[8];
            #pragma unroll
            for (int m = 0; m < 8; m++) {
                float f0, f1;
                unpack2(acc[m][j], f0, f1);
                f0 = tanha(f0); f1 = tanha(f1);
                c0[m] = f0; c1[m] = f1;
                pacc[2 * j]     += f0 * wev[m];
                pacc[2 * j + 1] += f1 * wev[m];
            }
            if (go >= 8) {
                int node0 = n0 + nb0 + 2 * j;
                int c = out0 - 64;
                if (node0 < NN) {
                    float4* d = reinterpret_cast<float4*>(g_v + (size_t)node0 * DH + c);
                    d[0] = make_float4(c0[0], c0[1], c0[2], c0[3]);
                    d[1] = make_float4(c0[4], c0[5], c0[6], c0[7]);
                }
                if (node0 + 1 < NN) {
                    float4* d = reinterpret_cast<float4*>(g_v + (size_t)(node0 + 1) * DH + c);
                    d[0] = make_float4(c1[0], c1[1], c1[2], c1[3]);
                    d[1] = make_float4(c1[4], c1[5], c1[6], c1[7]);
                }
            }
        }

        #pragma unroll
        for (int o = 1; o < 8; o <<= 1) {
            #pragma unroll
            for (int n = 0; n < 8; n++)
                pacc[n] += __shfl_xor_sync(0xffffffffu, pacc[n], o);
        }
        if (go == 0) {
            int node0 = n0 + nb0;
            #pragma unroll
            for (int n = 0; n < 8; n++)
                if (node0 + n < NN) g_p[node0 + n] = pacc[n];
        }
    }
}

// ---------------- per-row softmax + aggregation + std-normalize ----------------
// Single pass: softmax shift uses constant 1 (tanh < 1 always) instead of the
// row max — mathematically identical, numerically safe (weights in [e^-2, 1]).
// Edge loop unrolled x2 for 2 independent v-row gathers in flight.
__global__ void gat_rows(const float* __restrict__ beptr, float* __restrict__ out)
{
    const int warp = (blockIdx.x * blockDim.x + threadIdx.x) >> 5;
    const int lane = threadIdx.x & 31;
    if (warp >= NN) return;

    const float be = __ldg(beptr);
    const int s = g_rowptr[warp];
    const int e = g_rowptr[warp + 1];
    const float pb = __ldg(&g_p[warp]) + be;   // p_i + be

    float acc0 = 0.f, acc1 = 0.f, den = 0.f;
    int j = s;
    for (; j + 2 <= e; j += 2) {
        const int d0 = g_dst[j];
        const int d1 = g_dst[j + 1];
        const float w0 = __expf(tanha(pb + g_p[d0]) - 1.0f);
        const float w1 = __expf(tanha(pb + g_p[d1]) - 1.0f);
        const float2 v0 = reinterpret_cast<const float2*>(g_v + (size_t)d0 * DH)[lane];
        const float2 v1 = reinterpret_cast<const float2*>(g_v + (size_t)d1 * DH)[lane];
        den  += w0 + w1;
        acc0 += w0 * v0.x + w1 * v1.x;
        acc1 += w0 * v0.y + w1 * v1.y;
    }
    if (j < e) {
        const int dd = g_dst[j];
        const float w = __expf(tanha(pb + g_p[dd]) - 1.0f);
        const float2 vv = reinterpret_cast<const float2*>(g_v + (size_t)dd * DH)[lane];
        den  += w;
        acc0 += w * vv.x;
        acc1 += w * vv.y;
    }
    const float inv = 1.f / den;
    acc0 *= inv; acc1 *= inv;

    float sum = acc0 + acc1;
    #pragma unroll
    for (int o = 16; o; o >>= 1) sum += __shfl_xor_sync(0xffffffffu, sum, o);
    const float mean = sum * (1.f / 64.f);
    float d0 = acc0 - mean, d1 = acc1 - mean;
    float ss = d0 * d0 + d1 * d1;
    #pragma unroll
    for (int o = 16; o; o >>= 1) ss += __shfl_xor_sync(0xffffffffu, ss, o);
    const float istd = rsqrtf(ss * (1.f / 63.f));

    out[(size_t)warp * DH + 2 * lane]     = acc0 * istd;
    out[(size_t)warp * DH + 2 * lane + 1] = acc1 * istd;
}

// ---------------- launch ----------------
extern "C" void kernel_launch(void* const* d_in, const int* in_sizes, int n_in,
                              void* d_out, int out_size)
{
    const float* h   = (const float*)d_in[0];
    const int*   ei  = (const int*)d_in[1];
    const int*   src = ei;
    const int*   dst = ei + EE;
    const float* W11 = (const float*)d_in[2];
    const float* b11 = (const float*)d_in[3];
    const float* W12 = (const float*)d_in[4];
    const float* b12 = (const float*)d_in[5];
    const float* W13 = (const float*)d_in[6];
    const float* b13 = (const float*)d_in[7];
    const float* W21 = (const float*)d_in[8];
    const float* b21 = (const float*)d_in[9];
    const float* W22 = (const float*)d_in[10];
    const float* b22 = (const float*)d_in[11];
    const float* W23 = (const float*)d_in[12];
    const float* b23 = (const float*)d_in[13];
    float* out = (float*)d_out;

    // ---- CSR build ----
    k_zero_counts<<<(NN + 255) / 256, 256>>>();
    k_count<<<(EE + 255) / 256, 256>>>(src);
    k_blockscan<<<SCAN_G, SCAN_B>>>();
    k_bsum_scan<<<1, 128>>>();
    k_addoff<<<SCAN_G, SCAN_B>>>();
    k_scatter<<<(EE + 255) / 256, 256>>>(src, dst);

    // ---- layer 1 ----
    {
        constexpr int DIN = 128;
        size_t smem = (size_t)(2 * DIN * 132) * sizeof(float);
        cudaFuncSetAttribute(node_transform2<DIN>,
                             cudaFuncAttributeMaxDynamicSharedMemorySize, (int)smem);
        node_transform2<DIN><<<148, 256, smem>>>(h, W11, b11, W12, W13, b13);
        gat_rows<<<(NN * 32 + 255) / 256, 256>>>(b12, g_h1);
    }

    // ---- layer 2 ----
    {
        constexpr int DIN = 64;
        size_t smem = (size_t)(2 * DIN * 132) * sizeof(float);
        cudaFuncSetAttribute(node_transform2<DIN>,
                             cudaFuncAttributeMaxDynamicSharedMemorySize, (int)smem);
        node_transform2<DIN><<<296, 256, smem>>>(g_h1, W21, b21, W22, W23, b23);
        gat_rows<<<(NN * 32 + 255) / 256, 256>>>(b22, out);
    }
}

// round 17
// speedup vs baseline: 1.4307x; 1.0662x over previous
#include <cuda_runtime.h>
#include <cuda_bf16.h>
#include <math.h>

#define NN 100000
#define EE 1600000
#define DH 64

#define SCAN_B 1024
#define SCAN_G ((NN + SCAN_B - 1) / SCAN_B)   // 98

// ---------------- scratch ----------------
__device__ int   g_rowptr[NN + 1];
__device__ int   g_wp[NN];
__device__ int   g_dst[EE];
__device__ int   g_bsum[SCAN_G];
__device__ int   g_boff[SCAN_G];
__device__ float g_p[NN];
__device__ float g_v[(size_t)NN * DH];
__device__ float g_h1[(size_t)NN * DH];

// ---------------- helpers ----------------
__device__ __forceinline__ float tanha(float x) {
    float y;
    asm("tanh.approx.f32 %0, %1;" : "=f"(y) : "f"(x));
    return y;
}

#define FMA2(d, a, b) \
    asm("fma.rn.f32x2 %0, %1, %2, %0;" : "+l"(d) : "l"(a), "l"(b))

__device__ __forceinline__ unsigned long long pack_dup(float f) {
    unsigned long long r;
    unsigned u = __float_as_uint(f);
    asm("mov.b64 %0, {%1, %2};" : "=l"(r) : "r"(u), "r"(u));
    return r;
}
__device__ __forceinline__ void unpack2(unsigned long long v, float& lo, float& hi) {
    unsigned a, b;
    asm("mov.b64 {%0, %1}, %2;" : "=r"(a), "=r"(b) : "l"(v));
    lo = __uint_as_float(a);
    hi = __uint_as_float(b);
}

// ---------------- CSR build ----------------
__global__ void k_zero_counts() {
    int i = blockIdx.x * blockDim.x + threadIdx.x;
    if (i < NN) g_wp[i] = 0;
}

__global__ void k_count(const int* __restrict__ src) {
    int j = blockIdx.x * blockDim.x + threadIdx.x;
    if (j < EE) atomicAdd(&g_wp[src[j]], 1);
}

__global__ void k_blockscan() {
    __shared__ int wsum[32];
    const int tid = threadIdx.x;
    const int i = blockIdx.x * SCAN_B + tid;
    const int lane = tid & 31, warp = tid >> 5;

    int v = (i < NN) ? g_wp[i] : 0;
    int s = v;
    #pragma unroll
    for (int o = 1; o < 32; o <<= 1) {
        int t = __shfl_up_sync(0xffffffffu, s, o);
        if (lane >= o) s += t;
    }
    if (lane == 31) wsum[warp] = s;
    __syncthreads();
    if (warp == 0) {
        int ws = wsum[lane];
        #pragma unroll
        for (int o = 1; o < 32; o <<= 1) {
            int t = __shfl_up_sync(0xffffffffu, ws, o);
            if (lane >= o) ws += t;
        }
        wsum[lane] = ws;
    }
    __syncthreads();
    int base = (warp == 0) ? 0 : wsum[warp - 1];
    int excl = base + s - v;
    if (i < NN) g_rowptr[i] = excl;
    if (tid == SCAN_B - 1) g_bsum[blockIdx.x] = excl + v;
}

__global__ void k_bsum_scan() {
    __shared__ int wsum[4];
    const int tid = threadIdx.x;
    const int lane = tid & 31, warp = tid >> 5;
    int v = (tid < SCAN_G) ? g_bsum[tid] : 0;
    int s = v;
    #pragma unroll
    for (int o = 1; o < 32; o <<= 1) {
        int t = __shfl_up_sync(0xffffffffu, s, o);
        if (lane >= o) s += t;
    }
    if (lane == 31) wsum[warp] = s;
    __syncthreads();
    int base = 0;
    for (int w = 0; w < warp; w++) base += wsum[w];
    if (tid < SCAN_G) g_boff[tid] = base + s - v;
}

__global__ void k_addoff() {
    const int i = blockIdx.x * SCAN_B + threadIdx.x;
    if (i < NN) {
        int r = g_rowptr[i] + g_boff[blockIdx.x];
        g_rowptr[i] = r;
        g_wp[i] = r;
    }
    if (i == 0) g_rowptr[NN] = EE;
}

__global__ void k_scatter(const int* __restrict__ src, const int* __restrict__ dst) {
    int j = blockIdx.x * blockDim.x + threadIdx.x;
    if (j < EE) {
        int pos = atomicAdd(&g_wp[src[j]], 1);
        g_dst[pos] = dst[j];
    }
}

// ---------------- fused node transform (register-tiled, FFMA2) ----------------
template <int DIN>
__global__ __launch_bounds__(256, 1)
void node_transform2(const float* __restrict__ x,
                     const float* __restrict__ Wa, const float* __restrict__ ba,
                     const float* __restrict__ we,
                     const float* __restrict__ Wv, const float* __restrict__ bv)
{
    constexpr int WS = 132;
    extern __shared__ float sm[];
    float* Wt = sm;
    float* Xt = sm + DIN * WS;

    const int tid  = threadIdx.x;
    const int go   = tid & 15;
    const int gn   = tid >> 4;
    const int out0 = go * 8;
    const int nb0  = gn * 8;

    for (int i = tid; i < 64 * DIN; i += 256) {
        int r = i / DIN, k = i - r * DIN;
        Wt[k * WS + r]      = Wa[i];
        Wt[k * WS + 64 + r] = Wv[i];
    }
    float bias[8], wev[8];
    #pragma unroll
    for (int m = 0; m < 8; m++) {
        int r = out0 + m;
        bias[m] = (r < 64) ? ba[r] : bv[r - 64];
        wev[m]  = (r < 64) ? we[r] : 0.f;
    }

    const int numTiles = (NN + 127) / 128;
    for (int tile = blockIdx.x; tile < numTiles; tile += gridDim.x) {
        const int n0 = tile * 128;
        __syncthreads();
        for (int i = tid; i < 128 * DIN; i += 256) {
            int n = i / DIN, k = i - n * DIN;
            int node = n0 + n;
            Xt[k * WS + n] = (node < NN) ? x[(size_t)node * DIN + k] : 0.f;
        }
        __syncthreads();

        unsigned long long acc[8][4];
        #pragma unroll
        for (int m = 0; m < 8; m++) {
            unsigned long long bb = pack_dup(bias[m]);
            acc[m][0] = bb; acc[m][1] = bb; acc[m][2] = bb; acc[m][3] = bb;
        }

        #pragma unroll 4
        for (int k = 0; k < DIN; k++) {
            const float4* wp = reinterpret_cast<const float4*>(Wt + k * WS + out0);
            float4 w0 = wp[0], w1 = wp[1];
            const ulonglong2* xp = reinterpret_cast<const ulonglong2*>(Xt + k * WS + nb0);
            ulonglong2 xa = xp[0], xb = xp[1];

            unsigned long long wq[8];
            wq[0] = pack_dup(w0.x); wq[1] = pack_dup(w0.y);
            wq[2] = pack_dup(w0.z); wq[3] = pack_dup(w0.w);
            wq[4] = pack_dup(w1.x); wq[5] = pack_dup(w1.y);
            wq[6] = pack_dup(w1.z); wq[7] = pack_dup(w1.w);

            #pragma unroll
            for (int m = 0; m < 8; m++) {
                FMA2(acc[m][0], wq[m], xa.x);
                FMA2(acc[m][1], wq[m], xa.y);
                FMA2(acc[m][2], wq[m], xb.x);
                FMA2(acc[m][3], wq[m], xb.y);
            }
        }

        float pacc[8];
        #pragma unroll
        for (int n = 0; n < 8; n++) pacc[n] = 0.f;

        #pragma unroll
        for (int j = 0; j < 4; j++) {
            float c0[8], c1[8];
            #pragma unroll
            for (int m = 0; m < 8; m++) {
                float f0, f1;
                unpack2(acc[m][j], f0, f1);
                f0 = tanha(f0); f1 = tanha(f1);
                c0[m] = f0; c1[m] = f1;
                pacc[2 * j]     += f0 * wev[m];
                pacc[2 * j + 1] += f1 * wev[m];
            }
            if (go >= 8) {
                int node0 = n0 + nb0 + 2 * j;
                int c = out0 - 64;
                if (node0 < NN) {
                    float4* d = reinterpret_cast<float4*>(g_v + (size_t)node0 * DH + c);
                    d[0] = make_float4(c0[0], c0[1], c0[2], c0[3]);
                    d[1] = make_float4(c0[4], c0[5], c0[6], c0[7]);
                }
                if (node0 + 1 < NN) {
                    float4* d = reinterpret_cast<float4*>(g_v + (size_t)(node0 + 1) * DH + c);
                    d[0] = make_float4(c1[0], c1[1], c1[2], c1[3]);
                    d[1] = make_float4(c1[4], c1[5], c1[6], c1[7]);
                }
            }
        }

        #pragma unroll
        for (int o = 1; o < 8; o <<= 1) {
            #pragma unroll
            for (int n = 0; n < 8; n++)
                pacc[n] += __shfl_xor_sync(0xffffffffu, pacc[n], o);
        }
        if (go == 0) {
            int node0 = n0 + nb0;
            #pragma unroll
            for (int n = 0; n < 8; n++)
                if (node0 + n < NN) g_p[node0 + n] = pacc[n];
        }
    }
}

// ---------------- per-row softmax + aggregation + std-normalize ----------------
// v2: TWO rows per warp. Half-warp (16 lanes) per row; each lane owns 4 columns
// (float4 gather). One tanh/exp warp-instr covers both halves' edges.
// Constant softmax shift 1 (tanh < 1) — exact, no max pass.
__global__ void gat_rows2(const float* __restrict__ beptr, float* __restrict__ out)
{
    const int gwarp = (blockIdx.x * blockDim.x + threadIdx.x) >> 5;
    const int lane  = threadIdx.x & 31;
    const int half  = lane >> 4;           // 0 or 1
    const int l16   = lane & 15;
    const int row   = gwarp * 2 + half;
    if (row >= NN) return;                 // NN even: whole warp exits together or not

    const float be = __ldg(beptr);
    const int s = g_rowptr[row];
    const int e = g_rowptr[row + 1];
    const float pb = __ldg(&g_p[row]) + be;

    float a0 = 0.f, a1 = 0.f, a2 = 0.f, a3 = 0.f, den = 0.f;
    int j = s;
    for (; j + 2 <= e; j += 2) {
        const int d0 = g_dst[j];
        const int d1 = g_dst[j + 1];
        const float w0 = __expf(tanha(pb + __ldg(&g_p[d0])) - 1.0f);
        const float w1 = __expf(tanha(pb + __ldg(&g_p[d1])) - 1.0f);
        const float4 v0 = reinterpret_cast<const float4*>(g_v + (size_t)d0 * DH)[l16];
        const float4 v1 = reinterpret_cast<const float4*>(g_v + (size_t)d1 * DH)[l16];
        den += w0 + w1;
        a0 += w0 * v0.x + w1 * v1.x;
        a1 += w0 * v0.y + w1 * v1.y;
        a2 += w0 * v0.z + w1 * v1.z;
        a3 += w0 * v0.w + w1 * v1.w;
    }
    if (j < e) {
        const int dd = g_dst[j];
        const float w = __expf(tanha(pb + __ldg(&g_p[dd])) - 1.0f);
        const float4 vv = reinterpret_cast<const float4*>(g_v + (size_t)dd * DH)[l16];
        den += w;
        a0 += w * vv.x; a1 += w * vv.y; a2 += w * vv.z; a3 += w * vv.w;
    }

    const float inv = 1.f / den;
    a0 *= inv; a1 *= inv; a2 *= inv; a3 *= inv;

    // mean over 64 values: per-lane partial (4 vals), reduce across 16 lanes.
    // xor offsets <= 8 keep the two halves independent.
    float sum = a0 + a1 + a2 + a3;
    #pragma unroll
    for (int o = 8; o; o >>= 1) sum += __shfl_xor_sync(0xffffffffu, sum, o);
    const float mean = sum * (1.f / 64.f);
    float e0 = a0 - mean, e1 = a1 - mean, e2 = a2 - mean, e3 = a3 - mean;
    float ss = e0 * e0 + e1 * e1 + e2 * e2 + e3 * e3;
    #pragma unroll
    for (int o = 8; o; o >>= 1) ss += __shfl_xor_sync(0xffffffffu, ss, o);
    const float istd = rsqrtf(ss * (1.f / 63.f));

    float4 r = make_float4(a0 * istd, a1 * istd, a2 * istd, a3 * istd);
    reinterpret_cast<float4*>(out + (size_t)row * DH)[l16] = r;
}

// ---------------- launch ----------------
extern "C" void kernel_launch(void* const* d_in, const int* in_sizes, int n_in,
                              void* d_out, int out_size)
{
    const float* h   = (const float*)d_in[0];
    const int*   ei  = (const int*)d_in[1];
    const int*   src = ei;
    const int*   dst = ei + EE;
    const float* W11 = (const float*)d_in[2];
    const float* b11 = (const float*)d_in[3];
    const float* W12 = (const float*)d_in[4];
    const float* b12 = (const float*)d_in[5];
    const float* W13 = (const float*)d_in[6];
    const float* b13 = (const float*)d_in[7];
    const float* W21 = (const float*)d_in[8];
    const float* b21 = (const float*)d_in[9];
    const float* W22 = (const float*)d_in[10];
    const float* b22 = (const float*)d_in[11];
    const float* W23 = (const float*)d_in[12];
    const float* b23 = (const float*)d_in[13];
    float* out = (float*)d_out;

    // ---- CSR build ----
    k_zero_counts<<<(NN + 255) / 256, 256>>>();
    k_count<<<(EE + 255) / 256, 256>>>(src);
    k_blockscan<<<SCAN_G, SCAN_B>>>();
    k_bsum_scan<<<1, 128>>>();
    k_addoff<<<SCAN_G, SCAN_B>>>();
    k_scatter<<<(EE + 255) / 256, 256>>>(src, dst);

    const int gatWarps = (NN + 1) / 2;                 // 50,000
    const int gatBlocks = (gatWarps * 32 + 255) / 256; // 6,250

    // ---- layer 1 ----
    {
        constexpr int DIN = 128;
        size_t smem = (size_t)(2 * DIN * 132) * sizeof(float);
        cudaFuncSetAttribute(node_transform2<DIN>,
                             cudaFuncAttributeMaxDynamicSharedMemorySize, (int)smem);
        node_transform2<DIN><<<148, 256, smem>>>(h, W11, b11, W12, W13, b13);
        gat_rows2<<<gatBlocks, 256>>>(b12, g_h1);
    }

    // ---- layer 2 ----
    {
        constexpr int DIN = 64;
        size_t smem = (size_t)(2 * DIN * 132) * sizeof(float);
        cudaFuncSetAttribute(node_transform2<DIN>,
                             cudaFuncAttributeMaxDynamicSharedMemorySize, (int)smem);
        node_transform2<DIN><<<296, 256, smem>>>(g_h1, W21, b21, W22, W23, b23);
        gat_rows2<<<gatBlocks, 256>>>(b22, out);
    }
}